// round 7
// baseline (speedup 1.0000x reference)
#include <cuda_runtime.h>
#include <cuda_fp16.h>
#include <cstdint>

// Problem constants (C=32,H=32,W=32,KS=3, B=32)
constexpr int NDIM = 32 * 32 * 32 + 1;   // 32769
constexpr int KDIM = 32 * 3 * 3;         // 288
constexpr int BDIM = 32;

// x transposed to [N, B] in fp16: each row is 64 B; one LDG.128 with 4-lane
// groups gathers EIGHT different rows per instruction.
__device__ __half g_xT[(size_t)NDIM * BDIM];

// ---------------------------------------------------------------------------
// Kernel 1: transpose + fp16-convert x [B, N] -> x_T [N, B].
// ---------------------------------------------------------------------------
__global__ __launch_bounds__(1024) void transpose_kernel(const float* __restrict__ x)
{
    __shared__ float tile[32][33];
    const int n0 = blockIdx.x * 32;
    const int tx = threadIdx.x;
    const int ty = threadIdx.y;

    const int n_load = n0 + tx;
    if (n_load < NDIM)
        tile[ty][tx] = __ldcs(&x[(size_t)ty * NDIM + n_load]);
    __syncthreads();

    const int n_store = n0 + ty;
    if (n_store < NDIM)
        g_xT[(size_t)n_store * BDIM + tx] = __float2half(tile[tx][ty]);
}

// ---------------------------------------------------------------------------
// Kernel 2 (persistent): warp handles row n; grid-stride over row-blocks.
// Structure as R6 (feed: one int4+float4 per group per q = 1 wf per 32 k's;
// gather: 4 LDG.128 per group per q). Changes this round:
//   - __ldcs on single-use feed streams (evict-first: protect x_T in L2)
//   - double-buffered s_acc -> one barrier per row-block instead of two
//   - L1 carveout maxed from host (x_T L1 hit rate -> less L2 traffic)
// ---------------------------------------------------------------------------
constexpr int WARPS_PER_BLOCK = 8;
constexpr int NBLK = (NDIM + WARPS_PER_BLOCK - 1) / WARPS_PER_BLOCK;  // 4097
constexpr int GRID = 148 * 4;                                          // 592
constexpr int QCNT = KDIM / 32;                                        // 9

__global__ __launch_bounds__(WARPS_PER_BLOCK * 32, 4)
void gather_dot_kernel(const float* __restrict__ vals,
                       const int*   __restrict__ cols,
                       float*       __restrict__ out)
{
    __shared__ float s_acc[2][WARPS_PER_BLOCK][33];   // double-buffered

    const int w    = threadIdx.x >> 5;
    const int lane = threadIdx.x & 31;
    const int g    = lane >> 2;   // group 0..7
    const int quad = lane & 3;    // 16B slice -> b = quad*8 .. quad*8+7

    int buf = 0;
    for (int rb = blockIdx.x; rb < NBLK; rb += GRID, buf ^= 1) {
        const int n = rb * WARPS_PER_BLOCK + w;

        float acc[8] = {0.f, 0.f, 0.f, 0.f, 0.f, 0.f, 0.f, 0.f};

        if (n < NDIM) {
            const int4*   cp = (const int4*)  (cols + (size_t)n * KDIM) + g;
            const float4* vp = (const float4*)(vals + (size_t)n * KDIM) + g;
            const char*   xb = (const char*)g_xT + quad * 16;

            int4   c = __ldcs(cp);          // feed q=0, streaming
            float4 v = __ldcs(vp);

            #pragma unroll
            for (int q = 0; q < QCNT; ++q) {
                // 4 independent gathers for this q (L2-cap-bound stream)
                uint4 h0 = __ldg((const uint4*)(xb + ((size_t)(unsigned)c.x << 6)));
                uint4 h1 = __ldg((const uint4*)(xb + ((size_t)(unsigned)c.y << 6)));
                uint4 h2 = __ldg((const uint4*)(xb + ((size_t)(unsigned)c.z << 6)));
                uint4 h3 = __ldg((const uint4*)(xb + ((size_t)(unsigned)c.w << 6)));
                float4 vc = v;

                // prefetch feed for q+1 while the gathers are in flight
                if (q + 1 < QCNT) {
                    c = __ldcs(cp + (q + 1) * 8);
                    v = __ldcs(vp + (q + 1) * 8);
                }

                {
                    float2 f0 = __half22float2(*(const __half2*)&h0.x);
                    float2 f1 = __half22float2(*(const __half2*)&h0.y);
                    float2 f2 = __half22float2(*(const __half2*)&h0.z);
                    float2 f3 = __half22float2(*(const __half2*)&h0.w);
                    acc[0] = fmaf(vc.x, f0.x, acc[0]); acc[1] = fmaf(vc.x, f0.y, acc[1]);
                    acc[2] = fmaf(vc.x, f1.x, acc[2]); acc[3] = fmaf(vc.x, f1.y, acc[3]);
                    acc[4] = fmaf(vc.x, f2.x, acc[4]); acc[5] = fmaf(vc.x, f2.y, acc[5]);
                    acc[6] = fmaf(vc.x, f3.x, acc[6]); acc[7] = fmaf(vc.x, f3.y, acc[7]);
                }
                {
                    float2 f0 = __half22float2(*(const __half2*)&h1.x);
                    float2 f1 = __half22float2(*(const __half2*)&h1.y);
                    float2 f2 = __half22float2(*(const __half2*)&h1.z);
                    float2 f3 = __half22float2(*(const __half2*)&h1.w);
                    acc[0] = fmaf(vc.y, f0.x, acc[0]); acc[1] = fmaf(vc.y, f0.y, acc[1]);
                    acc[2] = fmaf(vc.y, f1.x, acc[2]); acc[3] = fmaf(vc.y, f1.y, acc[3]);
                    acc[4] = fmaf(vc.y, f2.x, acc[4]); acc[5] = fmaf(vc.y, f2.y, acc[5]);
                    acc[6] = fmaf(vc.y, f3.x, acc[6]); acc[7] = fmaf(vc.y, f3.y, acc[7]);
                }
                {
                    float2 f0 = __half22float2(*(const __half2*)&h2.x);
                    float2 f1 = __half22float2(*(const __half2*)&h2.y);
                    float2 f2 = __half22float2(*(const __half2*)&h2.z);
                    float2 f3 = __half22float2(*(const __half2*)&h2.w);
                    acc[0] = fmaf(vc.z, f0.x, acc[0]); acc[1] = fmaf(vc.z, f0.y, acc[1]);
                    acc[2] = fmaf(vc.z, f1.x, acc[2]); acc[3] = fmaf(vc.z, f1.y, acc[3]);
                    acc[4] = fmaf(vc.z, f2.x, acc[4]); acc[5] = fmaf(vc.z, f2.y, acc[5]);
                    acc[6] = fmaf(vc.z, f3.x, acc[6]); acc[7] = fmaf(vc.z, f3.y, acc[7]);
                }
                {
                    float2 f0 = __half22float2(*(const __half2*)&h3.x);
                    float2 f1 = __half22float2(*(const __half2*)&h3.y);
                    float2 f2 = __half22float2(*(const __half2*)&h3.z);
                    float2 f3 = __half22float2(*(const __half2*)&h3.w);
                    acc[0] = fmaf(vc.w, f0.x, acc[0]); acc[1] = fmaf(vc.w, f0.y, acc[1]);
                    acc[2] = fmaf(vc.w, f1.x, acc[2]); acc[3] = fmaf(vc.w, f1.y, acc[3]);
                    acc[4] = fmaf(vc.w, f2.x, acc[4]); acc[5] = fmaf(vc.w, f2.y, acc[5]);
                    acc[6] = fmaf(vc.w, f3.x, acc[6]); acc[7] = fmaf(vc.w, f3.y, acc[7]);
                }
            }
        }

        // Butterfly-reduce over the 8 groups (lane bits [2:4]).
        #pragma unroll
        for (int s = 4; s < 32; s <<= 1) {
            #pragma unroll
            for (int j = 0; j < 8; ++j)
                acc[j] += __shfl_xor_sync(0xffffffffu, acc[j], s);
        }

        if (lane < 4) {
            #pragma unroll
            for (int j = 0; j < 8; ++j)
                s_acc[buf][w][lane * 8 + j] = acc[j];
        }
        __syncthreads();   // single barrier; buffers alternate per iteration

        // Sector-coalesced store: thread t -> b = t/8, j = t%8.
        const int b  = threadIdx.x >> 3;
        const int j  = threadIdx.x & 7;
        const int nn = rb * WARPS_PER_BLOCK + j;
        if (nn < NDIM)
            out[(size_t)b * NDIM + nn] = s_acc[buf][j][b];
    }
}

// ---------------------------------------------------------------------------
// kernel_launch: inputs per metadata order: x_affine (f32), vals (f32), cols (i32)
// ---------------------------------------------------------------------------
extern "C" void kernel_launch(void* const* d_in, const int* in_sizes, int n_in,
                              void* d_out, int out_size)
{
    const float* x    = (const float*)d_in[0];
    const float* vals = (const float*)d_in[1];
    const int*   cols = (const int*)  d_in[2];
    float*       out  = (float*)d_out;

    (void)in_sizes; (void)n_in; (void)out_size;

    // Maximize L1D carveout: gather kernel uses ~2 KB smem; every extra KB of
    // L1 raises the x_T hit rate and cuts L2 traffic (the binding resource).
    // Host-side attribute set, idempotent, not a graph node.
    static bool attr_set = false;
    if (!attr_set) {
        cudaFuncSetAttribute(gather_dot_kernel,
                             cudaFuncAttributePreferredSharedMemoryCarveout,
                             cudaSharedmemCarveoutMaxL1);
        attr_set = true;
    }

    {
        dim3 block(32, 32);
        dim3 grid((NDIM + 31) / 32);
        transpose_kernel<<<grid, block>>>(x);
    }
    {
        gather_dot_kernel<<<GRID, WARPS_PER_BLOCK * 32>>>(vals, cols, out);
    }
}

// round 8
// speedup vs baseline: 1.7951x; 1.7951x over previous
#include <cuda_runtime.h>
#include <cuda_fp16.h>
#include <cstdint>

// Problem constants (C=32,H=32,W=32,KS=3, B=32)
constexpr int NDIM = 32 * 32 * 32 + 1;   // 32769
constexpr int KDIM = 32 * 3 * 3;         // 288
constexpr int BDIM = 32;

// x transposed to [N, B] in fp16: each row is 64 B; one LDG.128 with 4-lane
// groups gathers EIGHT different rows per instruction.
__device__ __half g_xT[(size_t)NDIM * BDIM];

// ---------------------------------------------------------------------------
// Kernel 1: transpose + fp16-convert x [B, N] -> x_T [N, B].
// ---------------------------------------------------------------------------
__global__ __launch_bounds__(1024) void transpose_kernel(const float* __restrict__ x)
{
    __shared__ float tile[32][33];
    const int n0 = blockIdx.x * 32;
    const int tx = threadIdx.x;
    const int ty = threadIdx.y;

    const int n_load = n0 + tx;
    if (n_load < NDIM)
        tile[ty][tx] = x[(size_t)ty * NDIM + n_load];
    __syncthreads();

    const int n_store = n0 + ty;
    if (n_store < NDIM)
        g_xT[(size_t)n_store * BDIM + tx] = __float2half(tile[tx][ty]);
}

// ---------------------------------------------------------------------------
// Kernel 2 (persistent): warp handles row n; grid-stride over row-blocks.
// Feed: one int4 + one float4 per group per q (1 wf per 32 k's per array).
// Gather: 4 LDG.128 per group per q, each servicing 8 rows (64B fp16 rows).
// Carveout set to 10% from host: keeps 4 blocks/SM resident (R7's MaxL1
// carveout shrank smem below 4-block residency -> 2x regression) while
// granting ~205KB to L1D to convert L2 gather traffic into L1 hits.
// ---------------------------------------------------------------------------
constexpr int WARPS_PER_BLOCK = 8;
constexpr int NBLK = (NDIM + WARPS_PER_BLOCK - 1) / WARPS_PER_BLOCK;  // 4097
constexpr int GRID = 148 * 4;                                          // 592
constexpr int QCNT = KDIM / 32;                                        // 9

__global__ __launch_bounds__(WARPS_PER_BLOCK * 32, 4)
void gather_dot_kernel(const float* __restrict__ vals,
                       const int*   __restrict__ cols,
                       float*       __restrict__ out)
{
    __shared__ float s_acc[2][WARPS_PER_BLOCK][33];   // double-buffered

    const int w    = threadIdx.x >> 5;
    const int lane = threadIdx.x & 31;
    const int g    = lane >> 2;   // group 0..7
    const int quad = lane & 3;    // 16B slice -> b = quad*8 .. quad*8+7

    int buf = 0;
    for (int rb = blockIdx.x; rb < NBLK; rb += GRID, buf ^= 1) {
        const int n = rb * WARPS_PER_BLOCK + w;

        float acc[8] = {0.f, 0.f, 0.f, 0.f, 0.f, 0.f, 0.f, 0.f};

        if (n < NDIM) {
            const int4*   cp = (const int4*)  (cols + (size_t)n * KDIM) + g;
            const float4* vp = (const float4*)(vals + (size_t)n * KDIM) + g;
            const char*   xb = (const char*)g_xT + quad * 16;

            int4   c = __ldg(cp);          // feed q=0 (1 wf across warp)
            float4 v = __ldg(vp);

            #pragma unroll
            for (int q = 0; q < QCNT; ++q) {
                // 4 independent gathers for this q (the cap-bound stream)
                uint4 h0 = __ldg((const uint4*)(xb + ((size_t)(unsigned)c.x << 6)));
                uint4 h1 = __ldg((const uint4*)(xb + ((size_t)(unsigned)c.y << 6)));
                uint4 h2 = __ldg((const uint4*)(xb + ((size_t)(unsigned)c.z << 6)));
                uint4 h3 = __ldg((const uint4*)(xb + ((size_t)(unsigned)c.w << 6)));
                float4 vc = v;

                // prefetch feed for q+1 while the gathers are in flight
                if (q + 1 < QCNT) {
                    c = __ldg(cp + (q + 1) * 8);
                    v = __ldg(vp + (q + 1) * 8);
                }

                {
                    float2 f0 = __half22float2(*(const __half2*)&h0.x);
                    float2 f1 = __half22float2(*(const __half2*)&h0.y);
                    float2 f2 = __half22float2(*(const __half2*)&h0.z);
                    float2 f3 = __half22float2(*(const __half2*)&h0.w);
                    acc[0] = fmaf(vc.x, f0.x, acc[0]); acc[1] = fmaf(vc.x, f0.y, acc[1]);
                    acc[2] = fmaf(vc.x, f1.x, acc[2]); acc[3] = fmaf(vc.x, f1.y, acc[3]);
                    acc[4] = fmaf(vc.x, f2.x, acc[4]); acc[5] = fmaf(vc.x, f2.y, acc[5]);
                    acc[6] = fmaf(vc.x, f3.x, acc[6]); acc[7] = fmaf(vc.x, f3.y, acc[7]);
                }
                {
                    float2 f0 = __half22float2(*(const __half2*)&h1.x);
                    float2 f1 = __half22float2(*(const __half2*)&h1.y);
                    float2 f2 = __half22float2(*(const __half2*)&h1.z);
                    float2 f3 = __half22float2(*(const __half2*)&h1.w);
                    acc[0] = fmaf(vc.y, f0.x, acc[0]); acc[1] = fmaf(vc.y, f0.y, acc[1]);
                    acc[2] = fmaf(vc.y, f1.x, acc[2]); acc[3] = fmaf(vc.y, f1.y, acc[3]);
                    acc[4] = fmaf(vc.y, f2.x, acc[4]); acc[5] = fmaf(vc.y, f2.y, acc[5]);
                    acc[6] = fmaf(vc.y, f3.x, acc[6]); acc[7] = fmaf(vc.y, f3.y, acc[7]);
                }
                {
                    float2 f0 = __half22float2(*(const __half2*)&h2.x);
                    float2 f1 = __half22float2(*(const __half2*)&h2.y);
                    float2 f2 = __half22float2(*(const __half2*)&h2.z);
                    float2 f3 = __half22float2(*(const __half2*)&h2.w);
                    acc[0] = fmaf(vc.z, f0.x, acc[0]); acc[1] = fmaf(vc.z, f0.y, acc[1]);
                    acc[2] = fmaf(vc.z, f1.x, acc[2]); acc[3] = fmaf(vc.z, f1.y, acc[3]);
                    acc[4] = fmaf(vc.z, f2.x, acc[4]); acc[5] = fmaf(vc.z, f2.y, acc[5]);
                    acc[6] = fmaf(vc.z, f3.x, acc[6]); acc[7] = fmaf(vc.z, f3.y, acc[7]);
                }
                {
                    float2 f0 = __half22float2(*(const __half2*)&h3.x);
                    float2 f1 = __half22float2(*(const __half2*)&h3.y);
                    float2 f2 = __half22float2(*(const __half2*)&h3.z);
                    float2 f3 = __half22float2(*(const __half2*)&h3.w);
                    acc[0] = fmaf(vc.w, f0.x, acc[0]); acc[1] = fmaf(vc.w, f0.y, acc[1]);
                    acc[2] = fmaf(vc.w, f1.x, acc[2]); acc[3] = fmaf(vc.w, f1.y, acc[3]);
                    acc[4] = fmaf(vc.w, f2.x, acc[4]); acc[5] = fmaf(vc.w, f2.y, acc[5]);
                    acc[6] = fmaf(vc.w, f3.x, acc[6]); acc[7] = fmaf(vc.w, f3.y, acc[7]);
                }
            }
        }

        // Butterfly-reduce over the 8 groups (lane bits [2:4]).
        #pragma unroll
        for (int s = 4; s < 32; s <<= 1) {
            #pragma unroll
            for (int j = 0; j < 8; ++j)
                acc[j] += __shfl_xor_sync(0xffffffffu, acc[j], s);
        }

        if (lane < 4) {
            #pragma unroll
            for (int j = 0; j < 8; ++j)
                s_acc[buf][w][lane * 8 + j] = acc[j];
        }
        __syncthreads();   // single barrier; buffers alternate per iteration

        // Sector-coalesced store: thread t -> b = t/8, j = t%8.
        const int b  = threadIdx.x >> 3;
        const int j  = threadIdx.x & 7;
        const int nn = rb * WARPS_PER_BLOCK + j;
        if (nn < NDIM)
            out[(size_t)b * NDIM + nn] = s_acc[buf][j][b];
    }
}

// ---------------------------------------------------------------------------
// kernel_launch: inputs per metadata order: x_affine (f32), vals (f32), cols (i32)
// ---------------------------------------------------------------------------
extern "C" void kernel_launch(void* const* d_in, const int* in_sizes, int n_in,
                              void* d_out, int out_size)
{
    const float* x    = (const float*)d_in[0];
    const float* vals = (const float*)d_in[1];
    const int*   cols = (const int*)  d_in[2];
    float*       out  = (float*)d_out;

    (void)in_sizes; (void)n_in; (void)out_size;

    // Carveout = 10% (~23KB smem pool): fits 4 resident blocks (2.1KB each +
    // driver overhead) AND maximizes L1D (~205KB) for gather hit rate.
    // (R7's MaxL1 = 0% broke 4-block residency -> 2x regression.)
    static bool attr_set = false;
    if (!attr_set) {
        cudaFuncSetAttribute(gather_dot_kernel,
                             cudaFuncAttributePreferredSharedMemoryCarveout, 10);
        attr_set = true;
    }

    {
        dim3 block(32, 32);
        dim3 grid((NDIM + 31) / 32);
        transpose_kernel<<<grid, block>>>(x);
    }
    {
        gather_dot_kernel<<<GRID, WARPS_PER_BLOCK * 32>>>(vals, cols, out);
    }
}